// round 11
// baseline (speedup 1.0000x reference)
#include <cuda_runtime.h>
#include <math.h>

#define B    4
#define Q    100
#define C    80
#define HM   128
#define WM   128
#define PIX  (HM*WM)   // 16384
#define OUT  512
#define CCH  40        // classes per smem chunk (2 chunks of 40)

// ---------------------------------------------------------------------------
// Exp-form logistic with ACCURATE libdevice expf (~2 ulp), strict ops:
// sigmoid(x) = 1 / (1 + exp(-x)). Matches XLA's exp-form logistic expansion
// (libdevice __nv_expf) bit-for-bit if that's the lowering; within ~2 ulp of
// the tanh-rational lowering otherwise. (Round-8's fast __expf was ~1e-6 off.)
// ---------------------------------------------------------------------------
__device__ __forceinline__ float sigf(float x) {
    return __fdiv_rn(1.0f, __fadd_rn(1.0f, expf(-x)));
}

// Strict 2-tap dot in ascending-source-index order: w0*v0 + w1*v1, no fma.
__device__ __forceinline__ float dot2(float w0, float v0, float w1, float v1) {
    return __fadd_rn(__fmul_rn(w0, v0), __fmul_rn(w1, v1));
}

// ---------------------------------------------------------------------------
// Single fused kernel. grid (128 row-groups, B images) x 512 threads.
// Block g<127 produces output rows 4g+2..4g+5 (source rows g,g+1);
// block 127 produces rows {0,1,510,511} (renormalized single tap, wy=0/1).
// Phases: 1) classify queries; 2) counting-sort by class; 3) per 40-class
// chunk: per-class sigmoid MEANS for the 2 source rows (all 512 threads:
// 2 class-halves x 2 rows x 128 cols); 4) strict y-then-x interp + argmax.
// Output: class ids as FLOAT32.
// ---------------------------------------------------------------------------
__global__ __launch_bounds__(512) void fused_segpost(const float* __restrict__ logits,
                                                     const float* __restrict__ masks,
                                                     float* __restrict__ out)
{
    __shared__ float acc[2][CCH][WM];   // 40 KB: per-class MEANS for 2 source rows
    __shared__ int   s_cls[Q];
    __shared__ short s_q[Q];            // query ids grouped by class (ascending)
    __shared__ short s_off[C+1];        // class start offsets into s_q

    const int b   = blockIdx.y;
    const int g   = blockIdx.x;         // 0..127
    const int tid = threadIdx.x;        // 0..511

    // ---- phase 1: classify queries (strict '>' == first-max tie-break) ----
    if (tid < Q) {
        const float* l = logits + (size_t)(b*Q + tid)*C;
        float mx = l[0]; int id = 0;
        #pragma unroll 4
        for (int c = 1; c < C; c++) {
            float v = l[c];
            if (v > mx) { mx = v; id = c; }
        }
        s_cls[tid] = id;
    }
    __syncthreads();

    // ---- phase 2: counting-sort queries by class ----
    if (tid < C) {
        int n = 0;
        for (int q = 0; q < Q; q++) n += (s_cls[q] == tid);
        s_off[tid+1] = (short)n;
    }
    if (tid == 0) s_off[0] = 0;
    __syncthreads();
    if (tid == 0) {
        for (int c = 1; c <= C; c++) s_off[c] = (short)(s_off[c] + s_off[c-1]);
    }
    __syncthreads();
    if (tid < C) {
        int k = s_off[tid];
        for (int q = 0; q < Q; q++)
            if (s_cls[q] == tid) s_q[k++] = (short)q;
    }
    __syncthreads();

    // ---- geometry ----
    const bool edge  = (g == 127);
    const int  srcR0 = edge ? 0   : g;
    const int  srcR1 = edge ? 127 : g + 1;
    const int  r = tid >> 7;        // 0..3: output row within group
    const int  j = tid & 127;       // source column / 4-wide output strip
    int   outRow;
    float wy;
    if (!edge) { outRow = 4*g + 2 + r;           wy = 0.125f + 0.25f*(float)r; }
    else       { outRow = (r < 2) ? r : 508 + r; wy = (r < 2) ? 0.0f : 1.0f;   }
    const float wyc = 1.0f - wy;    // exact (binary fractions)
    const int xm1 = (j > 0)   ? j - 1 : 0;
    const int xp1 = (j < 127) ? j + 1 : 127;

    // phase-3 work split: all 512 threads (class-half x row x col)
    const int p3_half = tid >> 8;         // 0/1 -> classes [half*20, half*20+20)
    const int p3_row  = (tid >> 7) & 1;   // 0/1
    const int p3_col  = tid & 127;
    const int p3_sr   = p3_row ? srcR1 : srcR0;

    float b0 = -1.0f, b1 = -1.0f, b2 = -1.0f, b3 = -1.0f;
    int   i0 = 0, i1 = 0, i2 = 0, i3 = 0;

    // ---- phases 3+4, per 40-class chunk ----
    for (int chunk = 0; chunk < 2; chunk++) {
        const int c0 = chunk * CCH;
        __syncthreads();   // protect acc reuse from previous chunk's reads

        // phase 3: per-class sigmoid MEANS; ascending q == segment order;
        // divide before interpolation (reference order).
        {
            const float* mbase = masks + (size_t)b*Q*PIX + p3_sr*WM + p3_col;
            const int cbeg = p3_half * 20, cend = cbeg + 20;
            for (int c = cbeg; c < cend; c++) {
                const int beg = s_off[c0 + c];
                const int end = s_off[c0 + c + 1];
                float a = 0.0f;
                for (int iq = beg; iq < end; iq++) {
                    const int q = s_q[iq];
                    a = __fadd_rn(a, sigf(mbase[(size_t)q * PIX]));
                }
                const float n = fmaxf((float)(end - beg), 1.0f);
                acc[p3_row][c][p3_col] = __fdiv_rn(a, n);   // sums / max(cnt,1)
            }
        }
        __syncthreads();

        // phase 4: strict y-then-x interp + argmax (all 512 threads)
        #pragma unroll 4
        for (int c = 0; c < CCH; c++) {
            const float L0 = acc[0][c][xm1], L1 = acc[1][c][xm1];
            const float M0 = acc[0][c][j  ], M1 = acc[1][c][j  ];
            const float R0 = acc[0][c][xp1], R1 = acc[1][c][xp1];
            // y-interp: ascending source row order; exact single tap at wy=0/1.
            const float tL = dot2(wyc, L0, wy, L1);
            const float tM = dot2(wyc, M0, wy, M1);
            const float tR = dot2(wyc, R0, wy, R1);
            // x-interp: ascending source col order; renormalized single tap at edges.
            float v0, v1, v2, v3;
            if (j == 0) { v0 = tM; v1 = tM; }
            else {
                v0 = dot2(0.375f, tL, 0.625f, tM);   // out col 4j
                v1 = dot2(0.125f, tL, 0.875f, tM);   // 4j+1
            }
            if (j == 127) { v2 = tM; v3 = tM; }
            else {
                v2 = dot2(0.875f, tM, 0.125f, tR);   // 4j+2
                v3 = dot2(0.625f, tM, 0.375f, tR);   // 4j+3
            }
            const int cid = c0 + c;
            if (v0 > b0) { b0 = v0; i0 = cid; }
            if (v1 > b1) { b1 = v1; i1 = cid; }
            if (v2 > b2) { b2 = v2; i2 = cid; }
            if (v3 > b3) { b3 = v3; i3 = cid; }
        }
    }

    // FLOAT32 output: class indices as float values, 4 cols per thread
    float4 res;
    res.x = (float)i0; res.y = (float)i1; res.z = (float)i2; res.w = (float)i3;
    *(float4*)(out + ((size_t)(b*OUT + outRow)) * OUT + 4*j) = res;
}

// ---------------------------------------------------------------------------
extern "C" void kernel_launch(void* const* d_in, const int* in_sizes, int n_in,
                              void* d_out, int out_size) {
    // Identify inputs by size (element- or byte-count), any ordering:
    //   pred_logits: 32000 elems / 128000 bytes
    //   pred_masks : 6553600 elems / 26214400 bytes
    const float* logits = nullptr;
    const float* masks  = nullptr;
    for (int i = 0; i < n_in; i++) {
        const long s = in_sizes[i];
        if (s == 32000 || s == 128000)          logits = (const float*)d_in[i];
        else if (s == 6553600 || s == 26214400) masks  = (const float*)d_in[i];
    }
    if (!logits && n_in > 0) logits = (const float*)d_in[0];   // positional fallback
    if (!masks  && n_in > 2) masks  = (const float*)d_in[2];
    if (!logits || !masks) return;

    float* out = (float*)d_out;   // [4,512,512] class ids as float32

    fused_segpost<<<dim3(128, B), 512>>>(logits, masks, out);
}

// round 12
// speedup vs baseline: 1.2750x; 1.2750x over previous
#include <cuda_runtime.h>
#include <math.h>

#define B    4
#define Q    100
#define C    80
#define HM   128
#define WM   128
#define PIX  (HM*WM)   // 16384
#define OUT  512
#define CCH  40        // class-slots per smem chunk

// Accurate libdevice expf logistic — bit-exact vs reference (round-11 proven).
__device__ __forceinline__ float sigf(float x) {
    return __fdiv_rn(1.0f, __fadd_rn(1.0f, expf(-x)));
}
// Strict 2-tap dot, ascending source index, no fma contraction.
__device__ __forceinline__ float dot2(float w0, float v0, float w1, float v1) {
    return __fadd_rn(__fmul_rn(w0, v0), __fmul_rn(w1, v1));
}

// ---------------------------------------------------------------------------
// grid (128 row-groups, B images) x 512 threads.
// Block g<127: output rows 4g+2..4g+5 from source rows g,g+1;
// block 127: rows {0,1,510,511} (exact single-tap via wy=0/1).
// Phase 1: classify (4 threads/query + shfl merge, first-max tiebreak).
// Phase 2: compact occupied classes into slots; queries grouped per slot.
// Phase 3: per-slot sigmoid MEANS for the 2 source rows (row-interleaved smem).
// Phase 4: y-interp once per column, neighbors via warp shuffle (bit-identical),
//          strict x-interp dots, running argmax over occupied slots only.
// ---------------------------------------------------------------------------
__global__ __launch_bounds__(512) void fused_segpost(const float* __restrict__ logits,
                                                     const float* __restrict__ masks,
                                                     float* __restrict__ out)
{
    __shared__ float acc2[CCH][WM][2];  // 40 KB, rows interleaved for LDS.64
    __shared__ int   s_cls[Q];
    __shared__ int   s_qoff[Q];         // byte offsets q*PIX*4, grouped by slot
    __shared__ short s_off[C+1];        // slot -> start index into s_qoff
    __shared__ short s_cid[C];          // slot -> original class id
    __shared__ short s_cnt[C];          // per-class query count
    __shared__ short s_slot[C];         // class -> slot (-1 if empty)
    __shared__ int   s_nocc;

    const int b   = blockIdx.y;
    const int g   = blockIdx.x;     // 0..127
    const int tid = threadIdx.x;    // 0..511

    // ---- phase 1: classify, 4 threads per query, shfl merge ----
    {
        const int q = tid >> 2, sub = tid & 3;
        float mx = -1e30f; int id = 0;
        if (q < Q) {
            const float* l = logits + (b*Q + q)*C + sub*20;
            mx = l[0]; id = sub*20;
            #pragma unroll
            for (int c = 1; c < 20; c++) {
                float v = l[c];
                if (v > mx) { mx = v; id = sub*20 + c; }  // first-max within range
            }
        }
        #pragma unroll
        for (int d = 1; d < 4; d <<= 1) {   // partners share the same q
            float om = __shfl_xor_sync(0xffffffffu, mx, d);
            int   oi = __shfl_xor_sync(0xffffffffu, id, d);
            if (om > mx || (om == mx && oi < id)) { mx = om; id = oi; }
        }
        if (q < Q && sub == 0) s_cls[q] = id;
    }
    __syncthreads();

    // ---- phase 2: counts, compaction, grouped query offsets ----
    if (tid < C) {
        int n = 0;
        for (int q = 0; q < Q; q++) n += (s_cls[q] == tid);
        s_cnt[tid] = (short)n;
    }
    __syncthreads();
    if (tid == 0) {
        int ns = 0, a = 0;
        for (int c = 0; c < C; c++) {
            if (s_cnt[c] > 0) {
                s_slot[c]  = (short)ns;
                s_cid[ns]  = (short)c;
                s_off[ns]  = (short)a;
                a += s_cnt[c];
                ns++;
            } else s_slot[c] = -1;
        }
        s_off[ns] = (short)a;   // == Q
        s_nocc = ns;
    }
    __syncthreads();
    if (tid < C) {
        const int sl = s_slot[tid];
        if (sl >= 0) {
            int k = s_off[sl];
            for (int q = 0; q < Q; q++)
                if (s_cls[q] == tid) s_qoff[k++] = q * (PIX*4);   // ascending q
        }
    }
    __syncthreads();
    const int nocc = s_nocc;

    // ---- geometry ----
    const bool edge  = (g == 127);
    const int  srcR0 = edge ? 0   : g;
    const int  srcR1 = edge ? 127 : g + 1;
    const int  r = tid >> 7;        // output row within group
    const int  j = tid & 127;       // source column / 4-wide output strip
    int   outRow;
    float wy;
    if (!edge) { outRow = 4*g + 2 + r;           wy = 0.125f + 0.25f*(float)r; }
    else       { outRow = (r < 2) ? r : 508 + r; wy = (r < 2) ? 0.0f : 1.0f;   }
    const float wyc = 1.0f - wy;    // exact

    // warp-boundary fallback column (branchless)
    const int lane = tid & 31;
    int fb = j;
    if (lane == 0  && j > 0)   fb = j - 1;
    if (lane == 31 && j < 127) fb = j + 1;
    const bool isL0 = (lane == 0), isL31 = (lane == 31);

    // x-interp weights; image-edge columns become exact single taps (0,1)
    float wA0 = 0.375f, wA1 = 0.625f, wB0 = 0.125f, wB1 = 0.875f;
    float wC0 = 0.875f, wC1 = 0.125f, wD0 = 0.625f, wD1 = 0.375f;
    if (j == 0)   { wA0 = 0.0f; wA1 = 1.0f; wB0 = 0.0f; wB1 = 1.0f; }
    if (j == 127) { wC0 = 1.0f; wC1 = 0.0f; wD0 = 1.0f; wD1 = 0.0f; }

    // phase-3 thread mapping
    const int p3_col  = tid & 127;
    const int p3_row  = (tid >> 7) & 1;
    const int p3_half = tid >> 8;
    const int p3_sr   = p3_row ? srcR1 : srcR0;
    const char* mrow  = (const char*)masks
                      + (size_t)4 * ((size_t)(b*Q)*PIX + p3_sr*WM + p3_col);

    float b0 = -1.0f, b1 = -1.0f, b2 = -1.0f, b3 = -1.0f;
    int   i0 = 0, i1 = 0, i2 = 0, i3 = 0;

    // ---- phases 3+4, per slot-chunk ----
    for (int s0 = 0; s0 < nocc; s0 += CCH) {
        const int nc = min(CCH, nocc - s0);
        __syncthreads();   // protect acc2 reuse

        // phase 3: per-slot sigmoid MEANS (slot parity split across thread halves)
        for (int s = p3_half; s < nc; s += 2) {
            const int beg = s_off[s0 + s];
            const int end = s_off[s0 + s + 1];
            float a = 0.0f;
            for (int iq = beg; iq < end; iq++)
                a = __fadd_rn(a, sigf(*(const float*)(mrow + s_qoff[iq])));
            acc2[s][p3_col][p3_row] = __fdiv_rn(a, (float)(end - beg));
        }
        __syncthreads();

        // phase 4: y-interp + shuffle neighbors + strict x-interp + argmax
        #pragma unroll 4
        for (int s = 0; s < nc; s++) {
            const float2 M = *(const float2*)&acc2[s][j][0];
            const float2 F = *(const float2*)&acc2[s][fb][0];
            const float tM = dot2(wyc, M.x, wy, M.y);
            const float tF = dot2(wyc, F.x, wy, F.y);
            float tL = __shfl_up_sync(0xffffffffu, tM, 1);
            float tR = __shfl_down_sync(0xffffffffu, tM, 1);
            tL = isL0  ? tF : tL;   // bit-identical to direct computation
            tR = isL31 ? tF : tR;
            const float v0 = dot2(wA0, tL, wA1, tM);   // out col 4j
            const float v1 = dot2(wB0, tL, wB1, tM);   // 4j+1
            const float v2 = dot2(wC0, tM, wC1, tR);   // 4j+2
            const float v3 = dot2(wD0, tM, wD1, tR);   // 4j+3
            const int cid = s_cid[s0 + s];
            if (v0 > b0) { b0 = v0; i0 = cid; }
            if (v1 > b1) { b1 = v1; i1 = cid; }
            if (v2 > b2) { b2 = v2; i2 = cid; }
            if (v3 > b3) { b3 = v3; i3 = cid; }
        }
    }

    float4 res;
    res.x = (float)i0; res.y = (float)i1; res.z = (float)i2; res.w = (float)i3;
    *(float4*)(out + ((size_t)(b*OUT + outRow)) * OUT + 4*j) = res;
}

// ---------------------------------------------------------------------------
extern "C" void kernel_launch(void* const* d_in, const int* in_sizes, int n_in,
                              void* d_out, int out_size) {
    const float* logits = nullptr;
    const float* masks  = nullptr;
    for (int i = 0; i < n_in; i++) {
        const long s = in_sizes[i];
        if (s == 32000 || s == 128000)          logits = (const float*)d_in[i];
        else if (s == 6553600 || s == 26214400) masks  = (const float*)d_in[i];
    }
    if (!logits && n_in > 0) logits = (const float*)d_in[0];
    if (!masks  && n_in > 2) masks  = (const float*)d_in[2];
    if (!logits || !masks) return;

    float* out = (float*)d_out;   // [4,512,512] class ids as float32

    fused_segpost<<<dim3(128, B), 512>>>(logits, masks, out);
}

// round 14
// speedup vs baseline: 1.6069x; 1.2604x over previous
#include <cuda_runtime.h>
#include <math.h>

#define B    4
#define Q    100
#define C    80
#define HM   128
#define WM   128
#define PIX  (HM*WM)   // 16384
#define OUT  512
#define CCH  40        // slots per smem chunk in KB

// ---- metadata + mean-map globals (written every launch by K0/KA) ----
__device__ int   g_nocc[B];
__device__ int   g_cid[B][C];     // slot -> class id
__device__ int   g_off[B][C+1];   // slot -> start into g_qoff
__device__ int   g_qoff[B][Q];    // byte offsets q*PIX*4, grouped by slot, ascending q
__device__ __align__(16) float g_means[B][C][PIX];   // per-(image,slot) sigmoid means

// Accurate libdevice expf logistic — bit-exact vs reference (round-11 proven).
__device__ __forceinline__ float sigf(float x) {
    return __fdiv_rn(1.0f, __fadd_rn(1.0f, expf(-x)));
}
// Strict 2-tap dot, ascending source index, no fma contraction.
__device__ __forceinline__ float dot2(float w0, float v0, float w1, float v1) {
    return __fadd_rn(__fmul_rn(w0, v0), __fmul_rn(w1, v1));
}

// ---------------------------------------------------------------------------
// K0: classify all B*Q queries, compact occupied classes, build grouped
// query-offset lists. One block; runs once per launch.
// ---------------------------------------------------------------------------
__global__ __launch_bounds__(512) void k0_meta(const float* __restrict__ logits) {
    __shared__ int s_cls[B*Q];
    __shared__ int s_cnt[B*C];
    __shared__ int s_slot[B*C];
    const int tid = threadIdx.x;

    if (tid < B*Q) {
        const float* l = logits + tid*C;
        float mx = l[0]; int id = 0;
        #pragma unroll 4
        for (int c = 1; c < C; c++) {
            float v = l[c];
            if (v > mx) { mx = v; id = c; }   // strict > == first-max tie-break
        }
        s_cls[tid] = id;
    }
    __syncthreads();

    if (tid < B*C) {
        const int b = tid / C, c = tid % C;
        int n = 0;
        for (int q = 0; q < Q; q++) n += (s_cls[b*Q + q] == c);
        s_cnt[tid] = n;
    }
    __syncthreads();

    if (tid < B) {
        const int b = tid;
        int ns = 0, a = 0;
        for (int c = 0; c < C; c++) {
            const int n = s_cnt[b*C + c];
            if (n > 0) {
                s_slot[b*C + c] = ns;
                g_cid[b][ns] = c;
                g_off[b][ns] = a;
                a += n; ns++;
            } else s_slot[b*C + c] = -1;
        }
        g_off[b][ns] = a;   // == Q
        g_nocc[b] = ns;
    }
    __syncthreads();

    if (tid < B*C) {
        const int b = tid / C, c = tid % C;
        const int sl = s_slot[tid];
        if (sl >= 0) {
            int k = g_off[b][sl];
            for (int q = 0; q < Q; q++)
                if (s_cls[b*Q + q] == c) g_qoff[b][k++] = q * (PIX*4);  // ascending q
        }
    }
}

// ---------------------------------------------------------------------------
// KA: per-(image,slot) sigmoid MEAN maps -> g_means. grid (4 pix-quarters,
// C slots, B images) x 256 threads. Ascending-q sums, __fdiv_rn by count:
// bit-identical to the fused round-12 phase 3.
// ---------------------------------------------------------------------------
__global__ __launch_bounds__(256) void ka_means(const float* __restrict__ masks) {
    const int b    = blockIdx.z;
    const int slot = blockIdx.y;
    if (slot >= g_nocc[b]) return;

    const int tid   = threadIdx.x;
    const int base4 = blockIdx.x * 1024 + tid;   // float4 index, strides of 256
    const int beg   = g_off[b][slot];
    const int end   = g_off[b][slot+1];
    const float nf  = (float)(end - beg);
    const char* mb  = (const char*)(masks + (size_t)b*Q*PIX);

    float4 a0 = make_float4(0.f,0.f,0.f,0.f);
    float4 a1 = a0, a2 = a0, a3 = a0;

    for (int iq = beg; iq < end; iq++) {
        const char* mp = mb + g_qoff[b][iq];
        const float4 m0 = ((const float4*)mp)[base4      ];
        const float4 m1 = ((const float4*)mp)[base4 + 256];
        const float4 m2 = ((const float4*)mp)[base4 + 512];
        const float4 m3 = ((const float4*)mp)[base4 + 768];
        a0.x = __fadd_rn(a0.x, sigf(m0.x)); a0.y = __fadd_rn(a0.y, sigf(m0.y));
        a0.z = __fadd_rn(a0.z, sigf(m0.z)); a0.w = __fadd_rn(a0.w, sigf(m0.w));
        a1.x = __fadd_rn(a1.x, sigf(m1.x)); a1.y = __fadd_rn(a1.y, sigf(m1.y));
        a1.z = __fadd_rn(a1.z, sigf(m1.z)); a1.w = __fadd_rn(a1.w, sigf(m1.w));
        a2.x = __fadd_rn(a2.x, sigf(m2.x)); a2.y = __fadd_rn(a2.y, sigf(m2.y));
        a2.z = __fadd_rn(a2.z, sigf(m2.z)); a2.w = __fadd_rn(a2.w, sigf(m2.w));
        a3.x = __fadd_rn(a3.x, sigf(m3.x)); a3.y = __fadd_rn(a3.y, sigf(m3.y));
        a3.z = __fadd_rn(a3.z, sigf(m3.z)); a3.w = __fadd_rn(a3.w, sigf(m3.w));
    }
    #define DIV4(v) v.x=__fdiv_rn(v.x,nf); v.y=__fdiv_rn(v.y,nf); \
                    v.z=__fdiv_rn(v.z,nf); v.w=__fdiv_rn(v.w,nf);
    DIV4(a0) DIV4(a1) DIV4(a2) DIV4(a3)

    float4* op = (float4*)g_means[b][slot];
    op[base4      ] = a0;
    op[base4 + 256] = a1;
    op[base4 + 512] = a2;
    op[base4 + 768] = a3;
}

// ---------------------------------------------------------------------------
// KB: interp + argmax. grid (128 row-groups, B) x 512. Cooperative float4
// loads of the 2 source mean-rows per slot (L2-hot), then shuffle-based
// interp + argmax (bit-identical math to round 12).
// ---------------------------------------------------------------------------
__global__ __launch_bounds__(512) void kb_upargmax(float* __restrict__ out) {
    __shared__ float acc2[CCH][WM][2];  // 40 KB, source rows interleaved
    __shared__ int   s_cid[C];

    const int b   = blockIdx.y;
    const int g   = blockIdx.x;     // 0..127
    const int tid = threadIdx.x;    // 0..511

    const int nocc = g_nocc[b];
    if (tid < C) s_cid[tid] = g_cid[b][tid];

    // geometry
    const bool edge  = (g == 127);
    const int  srcR0 = edge ? 0   : g;
    const int  srcR1 = edge ? 127 : g + 1;
    const int  r = tid >> 7;
    const int  j = tid & 127;
    int   outRow;
    float wy;
    if (!edge) { outRow = 4*g + 2 + r;           wy = 0.125f + 0.25f*(float)r; }
    else       { outRow = (r < 2) ? r : 508 + r; wy = (r < 2) ? 0.0f : 1.0f;   }
    const float wyc = 1.0f - wy;

    const int lane = tid & 31;
    int fb = j;
    if (lane == 0  && j > 0)   fb = j - 1;
    if (lane == 31 && j < 127) fb = j + 1;
    const bool isL0 = (lane == 0), isL31 = (lane == 31);

    float wA0 = 0.375f, wA1 = 0.625f, wB0 = 0.125f, wB1 = 0.875f;
    float wC0 = 0.875f, wC1 = 0.125f, wD0 = 0.625f, wD1 = 0.375f;
    if (j == 0)   { wA0 = 0.0f; wA1 = 1.0f; wB0 = 0.0f; wB1 = 1.0f; }
    if (j == 127) { wC0 = 1.0f; wC1 = 0.0f; wD0 = 1.0f; wD1 = 0.0f; }

    float b0 = -1.0f, b1 = -1.0f, b2 = -1.0f, b3 = -1.0f;
    int   i0 = 0, i1 = 0, i2 = 0, i3 = 0;

    for (int s0 = 0; s0 < nocc; s0 += CCH) {
        const int nc = min(CCH, nocc - s0);
        __syncthreads();   // acc2 reuse barrier (also covers s_cid first pass)

        // load nc slots x 2 source rows as float4 (32 vec-loads per row)
        // i in [0, nc*64): slot s = i>>6, row = (i>>5)&1, x4 = i&31
        for (int i = tid; i < nc*64; i += 512) {
            const int s   = i >> 6;
            const int row = (i >> 5) & 1;
            const int x4  = i & 31;
            const int sr  = row ? srcR1 : srcR0;
            const float4 v = *(const float4*)&g_means[b][s0 + s][sr*WM + x4*4];
            const int col = x4 * 4;
            acc2[s][col  ][row] = v.x;
            acc2[s][col+1][row] = v.y;
            acc2[s][col+2][row] = v.z;
            acc2[s][col+3][row] = v.w;
        }
        __syncthreads();

        #pragma unroll 4
        for (int s = 0; s < nc; s++) {
            const float2 M = *(const float2*)&acc2[s][j][0];
            const float2 F = *(const float2*)&acc2[s][fb][0];
            const float tM = dot2(wyc, M.x, wy, M.y);
            const float tF = dot2(wyc, F.x, wy, F.y);
            float tL = __shfl_up_sync(0xffffffffu, tM, 1);
            float tR = __shfl_down_sync(0xffffffffu, tM, 1);
            tL = isL0  ? tF : tL;   // bit-identical to direct computation
            tR = isL31 ? tF : tR;
            const float v0 = dot2(wA0, tL, wA1, tM);
            const float v1 = dot2(wB0, tL, wB1, tM);
            const float v2 = dot2(wC0, tM, wC1, tR);
            const float v3 = dot2(wD0, tM, wD1, tR);
            const int cid = s_cid[s0 + s];
            if (v0 > b0) { b0 = v0; i0 = cid; }
            if (v1 > b1) { b1 = v1; i1 = cid; }
            if (v2 > b2) { b2 = v2; i2 = cid; }
            if (v3 > b3) { b3 = v3; i3 = cid; }
        }
    }

    float4 res;
    res.x = (float)i0; res.y = (float)i1; res.z = (float)i2; res.w = (float)i3;
    *(float4*)(out + ((size_t)(b*OUT + outRow)) * OUT + 4*j) = res;
}

// ---------------------------------------------------------------------------
extern "C" void kernel_launch(void* const* d_in, const int* in_sizes, int n_in,
                              void* d_out, int out_size) {
    const float* logits = nullptr;
    const float* masks  = nullptr;
    for (int i = 0; i < n_in; i++) {
        const long s = in_sizes[i];
        if (s == 32000 || s == 128000)          logits = (const float*)d_in[i];
        else if (s == 6553600 || s == 26214400) masks  = (const float*)d_in[i];
    }
    if (!logits && n_in > 0) logits = (const float*)d_in[0];
    if (!masks  && n_in > 2) masks  = (const float*)d_in[2];
    if (!logits || !masks) return;

    float* out = (float*)d_out;   // [4,512,512] class ids as float32

    k0_meta    <<<1, 512>>>(logits);
    ka_means   <<<dim3(4, C, B), 256>>>(masks);
    kb_upargmax<<<dim3(128, B), 512>>>(out);
}

// round 17
// speedup vs baseline: 1.8805x; 1.1702x over previous
#include <cuda_runtime.h>
#include <math.h>

#define B    4
#define Q    100
#define C    80
#define HM   128
#define WM   128
#define PIX  (HM*WM)   // 16384
#define OUT  512
#define CCH  40        // slots per smem chunk in KB

// ---- metadata + mean-map globals (written every launch by K0/KA) ----
__device__ int   g_nocc[B];
__device__ int   g_cid[B][C];     // slot -> class id
__device__ int   g_off[B][C+1];   // slot -> start into g_qoff
__device__ int   g_qoff[B][Q];    // byte offsets q*PIX*4, grouped by slot, ascending q
__device__ __align__(16) float g_means[B][C][PIX];   // per-(image,slot) sigmoid means

// Accurate libdevice expf logistic — bit-exact vs reference (round-11 proven).
__device__ __forceinline__ float sigf(float x) {
    return __fdiv_rn(1.0f, __fadd_rn(1.0f, expf(-x)));
}
// Strict 2-tap dot, ascending source index, no fma contraction.
__device__ __forceinline__ float dot2(float w0, float v0, float w1, float v1) {
    return __fadd_rn(__fmul_rn(w0, v0), __fmul_rn(w1, v1));
}

// ---------------------------------------------------------------------------
// K0: metadata. grid = B blocks (one image each) x 256 threads.
// Classification: 1 thread/query, 20 fully-unrolled float4 loads (MLP~20),
// then ascending in-register scan (strict '>' == first-max tie-break, same
// compare order as before => bit-identical classes).
// ---------------------------------------------------------------------------
__global__ __launch_bounds__(256) void k0_meta(const float* __restrict__ logits) {
    __shared__ int s_cls[Q];
    __shared__ int s_cnt[C];
    __shared__ int s_slot[C];
    const int b   = blockIdx.x;
    const int tid = threadIdx.x;

    if (tid < Q) {
        const float4* l4 = (const float4*)(logits + (size_t)(b*Q + tid)*C);
        float4 v[20];
        #pragma unroll
        for (int k = 0; k < 20; k++) v[k] = l4[k];   // independent LDG.128s
        float mx = v[0].x; int id = 0;
        #pragma unroll
        for (int k = 0; k < 20; k++) {
            const int c4 = k*4;
            if (v[k].x > mx) { mx = v[k].x; id = c4;     }
            if (v[k].y > mx) { mx = v[k].y; id = c4 + 1; }
            if (v[k].z > mx) { mx = v[k].z; id = c4 + 2; }
            if (v[k].w > mx) { mx = v[k].w; id = c4 + 3; }
        }
        s_cls[tid] = id;
    }
    __syncthreads();

    if (tid < C) {
        int n = 0;
        for (int q = 0; q < Q; q++) n += (s_cls[q] == tid);
        s_cnt[tid] = n;
    }
    __syncthreads();

    if (tid == 0) {
        int ns = 0, a = 0;
        for (int c = 0; c < C; c++) {
            const int n = s_cnt[c];
            if (n > 0) {
                s_slot[c] = ns;
                g_cid[b][ns] = c;
                g_off[b][ns] = a;
                a += n; ns++;
            } else s_slot[c] = -1;
        }
        g_off[b][ns] = a;   // == Q
        g_nocc[b] = ns;
    }
    __syncthreads();

    if (tid < C) {
        const int sl = s_slot[tid];
        if (sl >= 0) {
            int k = g_off[b][sl];
            for (int q = 0; q < Q; q++)
                if (s_cls[q] == tid) g_qoff[b][k++] = q * (PIX*4);  // ascending q
        }
    }
}

// ---------------------------------------------------------------------------
// KA: per-(image,slot) sigmoid MEAN maps -> g_means. grid (4 pix-quarters,
// C slots, B images) x 256 threads. Ascending-q sums, __fdiv_rn by count:
// bit-identical to the fused round-12 phase 3.
// ---------------------------------------------------------------------------
__global__ __launch_bounds__(256) void ka_means(const float* __restrict__ masks) {
    const int b    = blockIdx.z;
    const int slot = blockIdx.y;
    if (slot >= g_nocc[b]) return;

    const int tid   = threadIdx.x;
    const int base4 = blockIdx.x * 1024 + tid;   // float4 index, strides of 256
    const int beg   = g_off[b][slot];
    const int end   = g_off[b][slot+1];
    const float nf  = (float)(end - beg);
    const char* mb  = (const char*)(masks + (size_t)b*Q*PIX);

    float4 a0 = make_float4(0.f,0.f,0.f,0.f);
    float4 a1 = a0, a2 = a0, a3 = a0;

    for (int iq = beg; iq < end; iq++) {
        const char* mp = mb + g_qoff[b][iq];
        const float4 m0 = ((const float4*)mp)[base4      ];
        const float4 m1 = ((const float4*)mp)[base4 + 256];
        const float4 m2 = ((const float4*)mp)[base4 + 512];
        const float4 m3 = ((const float4*)mp)[base4 + 768];
        a0.x = __fadd_rn(a0.x, sigf(m0.x)); a0.y = __fadd_rn(a0.y, sigf(m0.y));
        a0.z = __fadd_rn(a0.z, sigf(m0.z)); a0.w = __fadd_rn(a0.w, sigf(m0.w));
        a1.x = __fadd_rn(a1.x, sigf(m1.x)); a1.y = __fadd_rn(a1.y, sigf(m1.y));
        a1.z = __fadd_rn(a1.z, sigf(m1.z)); a1.w = __fadd_rn(a1.w, sigf(m1.w));
        a2.x = __fadd_rn(a2.x, sigf(m2.x)); a2.y = __fadd_rn(a2.y, sigf(m2.y));
        a2.z = __fadd_rn(a2.z, sigf(m2.z)); a2.w = __fadd_rn(a2.w, sigf(m2.w));
        a3.x = __fadd_rn(a3.x, sigf(m3.x)); a3.y = __fadd_rn(a3.y, sigf(m3.y));
        a3.z = __fadd_rn(a3.z, sigf(m3.z)); a3.w = __fadd_rn(a3.w, sigf(m3.w));
    }
    #define DIV4(v) v.x=__fdiv_rn(v.x,nf); v.y=__fdiv_rn(v.y,nf); \
                    v.z=__fdiv_rn(v.z,nf); v.w=__fdiv_rn(v.w,nf);
    DIV4(a0) DIV4(a1) DIV4(a2) DIV4(a3)

    float4* op = (float4*)g_means[b][slot];
    op[base4      ] = a0;
    op[base4 + 256] = a1;
    op[base4 + 512] = a2;
    op[base4 + 768] = a3;
}

// ---------------------------------------------------------------------------
// KB: interp + argmax. grid (128 row-groups, B) x 512. Cooperative float4
// loads of the 2 source mean-rows per slot (L2-hot), then shuffle-based
// interp + argmax (bit-identical math to round 12).
// ---------------------------------------------------------------------------
__global__ __launch_bounds__(512) void kb_upargmax(float* __restrict__ out) {
    __shared__ float acc2[CCH][WM][2];  // 40 KB, source rows interleaved
    __shared__ int   s_cid[C];

    const int b   = blockIdx.y;
    const int g   = blockIdx.x;     // 0..127
    const int tid = threadIdx.x;    // 0..511

    const int nocc = g_nocc[b];
    if (tid < C) s_cid[tid] = g_cid[b][tid];

    // geometry
    const bool edge  = (g == 127);
    const int  srcR0 = edge ? 0   : g;
    const int  srcR1 = edge ? 127 : g + 1;
    const int  r = tid >> 7;
    const int  j = tid & 127;
    int   outRow;
    float wy;
    if (!edge) { outRow = 4*g + 2 + r;           wy = 0.125f + 0.25f*(float)r; }
    else       { outRow = (r < 2) ? r : 508 + r; wy = (r < 2) ? 0.0f : 1.0f;   }
    const float wyc = 1.0f - wy;

    const int lane = tid & 31;
    int fb = j;
    if (lane == 0  && j > 0)   fb = j - 1;
    if (lane == 31 && j < 127) fb = j + 1;
    const bool isL0 = (lane == 0), isL31 = (lane == 31);

    float wA0 = 0.375f, wA1 = 0.625f, wB0 = 0.125f, wB1 = 0.875f;
    float wC0 = 0.875f, wC1 = 0.125f, wD0 = 0.625f, wD1 = 0.375f;
    if (j == 0)   { wA0 = 0.0f; wA1 = 1.0f; wB0 = 0.0f; wB1 = 1.0f; }
    if (j == 127) { wC0 = 1.0f; wC1 = 0.0f; wD0 = 1.0f; wD1 = 0.0f; }

    float b0 = -1.0f, b1 = -1.0f, b2 = -1.0f, b3 = -1.0f;
    int   i0 = 0, i1 = 0, i2 = 0, i3 = 0;

    for (int s0 = 0; s0 < nocc; s0 += CCH) {
        const int nc = min(CCH, nocc - s0);
        __syncthreads();   // acc2 reuse barrier (also covers s_cid first pass)

        // load nc slots x 2 source rows as float4 (32 vec-loads per row)
        for (int i = tid; i < nc*64; i += 512) {
            const int s   = i >> 6;
            const int row = (i >> 5) & 1;
            const int x4  = i & 31;
            const int sr  = row ? srcR1 : srcR0;
            const float4 v = *(const float4*)&g_means[b][s0 + s][sr*WM + x4*4];
            const int col = x4 * 4;
            acc2[s][col  ][row] = v.x;
            acc2[s][col+1][row] = v.y;
            acc2[s][col+2][row] = v.z;
            acc2[s][col+3][row] = v.w;
        }
        __syncthreads();

        #pragma unroll 4
        for (int s = 0; s < nc; s++) {
            const float2 M = *(const float2*)&acc2[s][j][0];
            const float2 F = *(const float2*)&acc2[s][fb][0];
            const float tM = dot2(wyc, M.x, wy, M.y);
            const float tF = dot2(wyc, F.x, wy, F.y);
            float tL = __shfl_up_sync(0xffffffffu, tM, 1);
            float tR = __shfl_down_sync(0xffffffffu, tM, 1);
            tL = isL0  ? tF : tL;   // bit-identical to direct computation
            tR = isL31 ? tF : tR;
            const float v0 = dot2(wA0, tL, wA1, tM);
            const float v1 = dot2(wB0, tL, wB1, tM);
            const float v2 = dot2(wC0, tM, wC1, tR);
            const float v3 = dot2(wD0, tM, wD1, tR);
            const int cid = s_cid[s0 + s];
            if (v0 > b0) { b0 = v0; i0 = cid; }
            if (v1 > b1) { b1 = v1; i1 = cid; }
            if (v2 > b2) { b2 = v2; i2 = cid; }
            if (v3 > b3) { b3 = v3; i3 = cid; }
        }
    }

    float4 res;
    res.x = (float)i0; res.y = (float)i1; res.z = (float)i2; res.w = (float)i3;
    *(float4*)(out + ((size_t)(b*OUT + outRow)) * OUT + 4*j) = res;
}

// ---------------------------------------------------------------------------
extern "C" void kernel_launch(void* const* d_in, const int* in_sizes, int n_in,
                              void* d_out, int out_size) {
    const float* logits = nullptr;
    const float* masks  = nullptr;
    for (int i = 0; i < n_in; i++) {
        const long s = in_sizes[i];
        if (s == 32000 || s == 128000)          logits = (const float*)d_in[i];
        else if (s == 6553600 || s == 26214400) masks  = (const float*)d_in[i];
    }
    if (!logits && n_in > 0) logits = (const float*)d_in[0];
    if (!masks  && n_in > 2) masks  = (const float*)d_in[2];
    if (!logits || !masks) return;

    float* out = (float*)d_out;   // [4,512,512] class ids as float32

    k0_meta    <<<B, 256>>>(logits);
    ka_means   <<<dim3(4, C, B), 256>>>(masks);
    kb_upargmax<<<dim3(128, B), 512>>>(out);
}